// round 1
// baseline (speedup 1.0000x reference)
#include <cuda_runtime.h>
#include <math.h>

// Problem constants
#define B 8
#define L 256
#define D 16
#define H 128      // H_NN
#define DFF 128
#define EPSV 1e-6f

// Scratch (device globals, allocation-free)
__device__ float g_v  [B * L * D];
__device__ float g_qa [B * L * H];
__device__ float g_qb [B * L * H];
__device__ float g_kbp[B * L * H];   // k@w1k + b1
__device__ float g_kap[B * L * H];   // k@w1q + b1

// ---------------------------------------------------------------------------
// Kernel 1: per-token projections + MLP pre-activations
// grid = B*L blocks, 128 threads
// ---------------------------------------------------------------------------
__global__ __launch_bounds__(128) void k_precompute(
    const float* __restrict__ x,
    const float* __restrict__ wq, const float* __restrict__ bq,
    const float* __restrict__ wk, const float* __restrict__ bk,
    const float* __restrict__ wv, const float* __restrict__ bv,
    const float* __restrict__ nn_w1, const float* __restrict__ nn_b1)
{
    __shared__ float xs[D], qs[D], ks[D];
    const int row = blockIdx.x;          // b*256 + l
    const int t = threadIdx.x;

    if (t < D) xs[t] = x[row * D + t];
    __syncthreads();

    if (t < D) {
        float a = bq[t];
        #pragma unroll
        for (int d = 0; d < D; ++d) a = fmaf(xs[d], wq[d * D + t], a);
        qs[t] = a;
    } else if (t < 2 * D) {
        const int c = t - D;
        float a = bk[c];
        #pragma unroll
        for (int d = 0; d < D; ++d) a = fmaf(xs[d], wk[d * D + c], a);
        ks[c] = a;
    } else if (t < 3 * D) {
        const int c = t - 2 * D;
        float a = bv[c];
        #pragma unroll
        for (int d = 0; d < D; ++d) a = fmaf(xs[d], wv[d * D + c], a);
        g_v[row * D + c] = a;
    }
    __syncthreads();

    const int h = t;  // 0..127
    float qa = 0.f, qb = 0.f;
    float kb = nn_b1[h], ka = nn_b1[h];
    #pragma unroll
    for (int d = 0; d < D; ++d) {
        const float w1q = nn_w1[d * H + h];
        const float w1k = nn_w1[(d + D) * H + h];
        qa = fmaf(qs[d], w1q, qa);
        qb = fmaf(qs[d], w1k, qb);
        kb = fmaf(ks[d], w1k, kb);
        ka = fmaf(ks[d], w1q, ka);
    }
    g_qa [row * H + h] = qa;
    g_qb [row * H + h] = qb;
    g_kbp[row * H + h] = kb;
    g_kap[row * H + h] = ka;
}

// ---------------------------------------------------------------------------
// Kernel 2: fused logits -> softmax -> ctx -> wo -> LN1 -> FFN -> LN2
// grid = B * (L/16) = 128 blocks, 256 threads, ~147KB dyn smem
// ---------------------------------------------------------------------------
#define TI 16       // query rows per block
#define TJ 64       // key rows per smem tile
#define HPAD 132    // padded row stride (floats) for qa/qb/kb/ka in smem

struct Smem {
    float qa[TI * HPAD];
    float qb[TI * HPAD];
    float kbp[TJ * HPAD];
    float kap[TJ * HPAD];
    float logits[TI * L];
    float v[L * D];
    float w2[H];
    float wo[D * D];
    float bo[D];
    float f1[D * DFF];
    float f1b[DFF];
    float f2[DFF * D];
    float f2b[D];
    float g1[D], be1[D], g2[D], be2[D];
    float xr[TI * D];
    float ctx[TI * D];
    float out1[TI * D];
    float hidden[TI * DFF];
};

__global__ __launch_bounds__(256, 1) void k_main(
    const float* __restrict__ x,
    const float* __restrict__ mask,
    const float* __restrict__ wo_g, const float* __restrict__ bo_g,
    const float* __restrict__ w2_g, const float* __restrict__ b2_g,
    const float* __restrict__ f1_g, const float* __restrict__ f1b_g,
    const float* __restrict__ f2_g, const float* __restrict__ f2b_g,
    const float* __restrict__ g1_g, const float* __restrict__ be1_g,
    const float* __restrict__ g2_g, const float* __restrict__ be2_g,
    float* __restrict__ out)
{
    extern __shared__ char smem_raw[];
    Smem* s = reinterpret_cast<Smem*>(smem_raw);

    const int tid   = threadIdx.x;
    const int b     = blockIdx.x >> 4;
    const int iBase = (blockIdx.x & 15) << 4;
    const int i_loc = tid >> 4;
    const int jl    = tid & 15;

    // ---------------- Phase 0: cooperative smem fills ----------------
    {
        // qa/qb for 16 query rows (padded stride)
        const float4* gqa = reinterpret_cast<const float4*>(g_qa + (b * L + iBase) * H);
        const float4* gqb = reinterpret_cast<const float4*>(g_qb + (b * L + iBase) * H);
        float4* sqa = reinterpret_cast<float4*>(s->qa);
        float4* sqb = reinterpret_cast<float4*>(s->qb);
        #pragma unroll
        for (int r = 0; r < 2; ++r) {
            const int idx = tid + 256 * r;          // < 512
            const int ir = idx >> 5, h4 = idx & 31;
            sqa[ir * 33 + h4] = gqa[idx];
            sqb[ir * 33 + h4] = gqb[idx];
        }
        // v (all 256 keys)
        const float4* gv = reinterpret_cast<const float4*>(g_v + b * L * D);
        float4* sv = reinterpret_cast<float4*>(s->v);
        #pragma unroll
        for (int r = 0; r < 4; ++r) sv[tid + 256 * r] = gv[tid + 256 * r];
        // weights
        #pragma unroll
        for (int r = 0; r < 8; ++r) {
            const int idx = tid + 256 * r;          // < 2048
            s->f1[idx] = f1_g[idx];
            s->f2[idx] = f2_g[idx];
        }
        if (tid < H)   { s->w2[tid] = w2_g[tid]; s->f1b[tid] = f1b_g[tid]; }
        s->wo[tid & 255] = wo_g[tid & 255];        // 256 threads -> 256 elems
        s->xr[tid]       = x[(b * L + iBase) * D + tid];
        if (tid < D) {
            s->bo[tid]  = bo_g[tid];  s->f2b[tid] = f2b_g[tid];
            s->g1[tid]  = g1_g[tid];  s->be1[tid] = be1_g[tid];
            s->g2[tid]  = g2_g[tid];  s->be2[tid] = be2_g[tid];
        }
    }

    // ---------------- Phase 1: pairwise-MLP logits ----------------
    const float4* qa_row = reinterpret_cast<const float4*>(s->qa + i_loc * HPAD);
    const float4* qb_row = reinterpret_cast<const float4*>(s->qb + i_loc * HPAD);
    const float4* w2v    = reinterpret_cast<const float4*>(s->w2);

    for (int jt = 0; jt < L / TJ; ++jt) {
        __syncthreads();  // previous tile consumers done / phase-0 writers done
        // stage kbp/kap tile [TJ=64][128] (padded) into smem
        {
            const float4* gk = reinterpret_cast<const float4*>(g_kbp + (b * L + jt * TJ) * H);
            const float4* ga = reinterpret_cast<const float4*>(g_kap + (b * L + jt * TJ) * H);
            float4* skb = reinterpret_cast<float4*>(s->kbp);
            float4* ska = reinterpret_cast<float4*>(s->kap);
            #pragma unroll
            for (int r = 0; r < 8; ++r) {
                const int idx = tid + 256 * r;      // < 2048
                const int jr = idx >> 5, h4 = idx & 31;
                skb[jr * 33 + h4] = gk[idx];
                ska[jr * 33 + h4] = ga[idx];
            }
        }
        __syncthreads();

        const float4* kb0 = reinterpret_cast<const float4*>(s->kbp) + jl * 33;
        const float4* ka0 = reinterpret_cast<const float4*>(s->kap) + jl * 33;

        float acc0 = 0.f, acc1 = 0.f, acc2 = 0.f, acc3 = 0.f;
        #pragma unroll 4
        for (int h4 = 0; h4 < 32; ++h4) {
            const float4 a  = qa_row[h4];
            const float4 bb = qb_row[h4];
            const float4 w  = w2v[h4];
            {
                const float4 kb = kb0[h4];
                const float4 ka = ka0[h4];
                acc0 = fmaf(fmaxf(a.x + kb.x, 0.f) + fmaxf(bb.x + ka.x, 0.f), w.x, acc0);
                acc0 = fmaf(fmaxf(a.y + kb.y, 0.f) + fmaxf(bb.y + ka.y, 0.f), w.y, acc0);
                acc0 = fmaf(fmaxf(a.z + kb.z, 0.f) + fmaxf(bb.z + ka.z, 0.f), w.z, acc0);
                acc0 = fmaf(fmaxf(a.w + kb.w, 0.f) + fmaxf(bb.w + ka.w, 0.f), w.w, acc0);
            }
            {
                const float4 kb = kb0[h4 + 16 * 33];
                const float4 ka = ka0[h4 + 16 * 33];
                acc1 = fmaf(fmaxf(a.x + kb.x, 0.f) + fmaxf(bb.x + ka.x, 0.f), w.x, acc1);
                acc1 = fmaf(fmaxf(a.y + kb.y, 0.f) + fmaxf(bb.y + ka.y, 0.f), w.y, acc1);
                acc1 = fmaf(fmaxf(a.z + kb.z, 0.f) + fmaxf(bb.z + ka.z, 0.f), w.z, acc1);
                acc1 = fmaf(fmaxf(a.w + kb.w, 0.f) + fmaxf(bb.w + ka.w, 0.f), w.w, acc1);
            }
            {
                const float4 kb = kb0[h4 + 32 * 33];
                const float4 ka = ka0[h4 + 32 * 33];
                acc2 = fmaf(fmaxf(a.x + kb.x, 0.f) + fmaxf(bb.x + ka.x, 0.f), w.x, acc2);
                acc2 = fmaf(fmaxf(a.y + kb.y, 0.f) + fmaxf(bb.y + ka.y, 0.f), w.y, acc2);
                acc2 = fmaf(fmaxf(a.z + kb.z, 0.f) + fmaxf(bb.z + ka.z, 0.f), w.z, acc2);
                acc2 = fmaf(fmaxf(a.w + kb.w, 0.f) + fmaxf(bb.w + ka.w, 0.f), w.w, acc2);
            }
            {
                const float4 kb = kb0[h4 + 48 * 33];
                const float4 ka = ka0[h4 + 48 * 33];
                acc3 = fmaf(fmaxf(a.x + kb.x, 0.f) + fmaxf(bb.x + ka.x, 0.f), w.x, acc3);
                acc3 = fmaf(fmaxf(a.y + kb.y, 0.f) + fmaxf(bb.y + ka.y, 0.f), w.y, acc3);
                acc3 = fmaf(fmaxf(a.z + kb.z, 0.f) + fmaxf(bb.z + ka.z, 0.f), w.z, acc3);
                acc3 = fmaf(fmaxf(a.w + kb.w, 0.f) + fmaxf(bb.w + ka.w, 0.f), w.w, acc3);
            }
        }
        const int jb = jt * TJ + jl;
        s->logits[i_loc * L + jb]      = acc0;
        s->logits[i_loc * L + jb + 16] = acc1;
        s->logits[i_loc * L + jb + 32] = acc2;
        s->logits[i_loc * L + jb + 48] = acc3;
    }
    __syncthreads();

    // ---------------- Phase 2: softmax (+mask, +2*b2) ----------------
    {
        const int warp = tid >> 5, lane = tid & 31;
        const float b2x2 = 2.f * b2_g[0];
        for (int r = warp; r < TI; r += 8) {
            const float* mrow = mask + (size_t)(b * L + iBase + r) * L;
            float vals[8];
            float mx = -INFINITY;
            #pragma unroll
            for (int t = 0; t < 8; ++t) {
                const int j = lane + 32 * t;
                const float lg = s->logits[r * L + j] + b2x2 + mrow[j] * (-1e9f);
                vals[t] = lg;
                mx = fmaxf(mx, lg);
            }
            #pragma unroll
            for (int m = 16; m > 0; m >>= 1)
                mx = fmaxf(mx, __shfl_xor_sync(0xffffffffu, mx, m));
            float sum = 0.f;
            #pragma unroll
            for (int t = 0; t < 8; ++t) { vals[t] = __expf(vals[t] - mx); sum += vals[t]; }
            #pragma unroll
            for (int m = 16; m > 0; m >>= 1)
                sum += __shfl_xor_sync(0xffffffffu, sum, m);
            const float inv = 1.f / sum;
            #pragma unroll
            for (int t = 0; t < 8; ++t)
                s->logits[r * L + lane + 32 * t] = vals[t] * inv;
        }
    }
    __syncthreads();

    // ---------------- Phase 3: ctx = attn @ v ; attn_out ; LN1 ----------------
    {
        float c = 0.f;
        const float* arow = s->logits + i_loc * L;
        #pragma unroll 8
        for (int j = 0; j < L; ++j)
            c = fmaf(arow[j], s->v[j * D + jl], c);
        s->ctx[i_loc * D + jl] = c;
    }
    __syncthreads();

    float out1v;
    {
        float ao = s->bo[jl];
        #pragma unroll
        for (int e = 0; e < D; ++e)
            ao = fmaf(s->ctx[i_loc * D + e], s->wo[e * D + jl], ao);
        const float hval = s->xr[i_loc * D + jl] + ao;   // RES=1 -> x + attn_out
        float m = hval, sq = hval * hval;
        #pragma unroll
        for (int msk = 8; msk > 0; msk >>= 1) {
            m  += __shfl_xor_sync(0xffffffffu, m,  msk);
            sq += __shfl_xor_sync(0xffffffffu, sq, msk);
        }
        m *= (1.f / 16.f);
        const float var = sq * (1.f / 16.f) - m * m;
        out1v = (hval - m) * rsqrtf(var + EPSV) * s->g1[jl] + s->be1[jl];
        s->out1[i_loc * D + jl] = out1v;
    }
    __syncthreads();

    // ---------------- Phase 4: FFN + LN2 ----------------
    {
        #pragma unroll
        for (int hh = 0; hh < 8; ++hh) {
            const int h = jl * 8 + hh;
            float acc = s->f1b[h];
            #pragma unroll
            for (int d = 0; d < D; ++d)
                acc = fmaf(s->out1[i_loc * D + d], s->f1[d * DFF + h], acc);
            s->hidden[i_loc * DFF + h] = fmaxf(acc, 0.f);
        }
    }
    __syncthreads();
    {
        float f = s->f2b[jl];
        const float* hrow = s->hidden + i_loc * DFF;
        #pragma unroll 8
        for (int h = 0; h < DFF; ++h)
            f = fmaf(hrow[h], s->f2[h * D + jl], f);
        const float hval = out1v + f;   // RES=1 -> out1 + ffn
        float m = hval, sq = hval * hval;
        #pragma unroll
        for (int msk = 8; msk > 0; msk >>= 1) {
            m  += __shfl_xor_sync(0xffffffffu, m,  msk);
            sq += __shfl_xor_sync(0xffffffffu, sq, msk);
        }
        m *= (1.f / 16.f);
        const float var = sq * (1.f / 16.f) - m * m;
        const float o = (hval - m) * rsqrtf(var + EPSV) * s->g2[jl] + s->be2[jl];
        out[(size_t)(b * L + iBase + i_loc) * D + jl] = o;
    }
}

// ---------------------------------------------------------------------------
extern "C" void kernel_launch(void* const* d_in, const int* in_sizes, int n_in,
                              void* d_out, int out_size)
{
    const float* x     = (const float*)d_in[0];
    const float* mask  = (const float*)d_in[1];
    const float* wq    = (const float*)d_in[2];
    const float* bq    = (const float*)d_in[3];
    const float* wk    = (const float*)d_in[4];
    const float* bk    = (const float*)d_in[5];
    const float* wv    = (const float*)d_in[6];
    const float* bv    = (const float*)d_in[7];
    const float* wo    = (const float*)d_in[8];
    const float* bo    = (const float*)d_in[9];
    const float* nn_w1 = (const float*)d_in[10];
    const float* nn_b1 = (const float*)d_in[11];
    const float* nn_w2 = (const float*)d_in[12];
    const float* nn_b2 = (const float*)d_in[13];
    const float* f1    = (const float*)d_in[14];
    const float* f1b   = (const float*)d_in[15];
    const float* f2    = (const float*)d_in[16];
    const float* f2b   = (const float*)d_in[17];
    const float* g1    = (const float*)d_in[18];
    const float* be1   = (const float*)d_in[19];
    const float* g2    = (const float*)d_in[20];
    const float* be2   = (const float*)d_in[21];
    float* out = (float*)d_out;

    cudaFuncSetAttribute(k_main, cudaFuncAttributeMaxDynamicSharedMemorySize,
                         (int)sizeof(Smem));

    k_precompute<<<B * L, 128>>>(x, wq, bq, wk, bk, wv, bv, nn_w1, nn_b1);
    k_main<<<B * (L / TI), 256, sizeof(Smem)>>>(
        x, mask, wo, bo, nn_w2, nn_b2, f1, f1b, f2, f2b, g1, be1, g2, be2, out);
}

// round 2
// speedup vs baseline: 1.1063x; 1.1063x over previous
#include <cuda_runtime.h>
#include <math.h>

// Problem constants
#define B 8
#define L 256
#define D 16
#define H 128      // H_NN
#define DFF 128
#define EPSV 1e-6f

#define TI 16       // query rows per block
#define TJ 64       // key rows per smem tile
#define HPAD 132    // padded row stride (floats) in smem

typedef unsigned long long u64;

// Scratch (device globals, allocation-free)
__device__ float g_v  [B * L * D];
__device__ float g_qa [B * L * H];
__device__ float g_qb [B * L * H];
__device__ float g_kbp[B * L * H];   // k@w1k + b1
__device__ float g_kap[B * L * H];   // k@w1q + b1

// ---------------- packed f32x2 helpers ----------------
__device__ __forceinline__ u64 add2(u64 a, u64 b) {
    u64 d; asm("add.rn.f32x2 %0,%1,%2;" : "=l"(d) : "l"(a), "l"(b)); return d;
}
__device__ __forceinline__ u64 fma2(u64 a, u64 b, u64 c) {
    u64 d; asm("fma.rn.f32x2 %0,%1,%2,%3;" : "=l"(d) : "l"(a), "l"(b), "l"(c)); return d;
}
__device__ __forceinline__ u64 relu2(u64 v) {
    float lo, hi;
    asm("mov.b64 {%0,%1}, %2;" : "=f"(lo), "=f"(hi) : "l"(v));
    lo = fmaxf(lo, 0.f); hi = fmaxf(hi, 0.f);
    u64 d; asm("mov.b64 %0,{%1,%2};" : "=l"(d) : "f"(lo), "f"(hi)); return d;
}
__device__ __forceinline__ float redu2(u64 v) {
    float lo, hi;
    asm("mov.b64 {%0,%1}, %2;" : "=f"(lo), "=f"(hi) : "l"(v));
    return lo + hi;
}

// ---------------------------------------------------------------------------
// Kernel 1: per-token projections + MLP pre-activations
// ---------------------------------------------------------------------------
__global__ __launch_bounds__(128) void k_precompute(
    const float* __restrict__ x,
    const float* __restrict__ wq, const float* __restrict__ bq,
    const float* __restrict__ wk, const float* __restrict__ bk,
    const float* __restrict__ wv, const float* __restrict__ bv,
    const float* __restrict__ nn_w1, const float* __restrict__ nn_b1)
{
    __shared__ float xs[D], qs[D], ks[D];
    const int row = blockIdx.x;          // b*256 + l
    const int t = threadIdx.x;

    if (t < D) xs[t] = x[row * D + t];
    __syncthreads();

    if (t < D) {
        float a = bq[t];
        #pragma unroll
        for (int d = 0; d < D; ++d) a = fmaf(xs[d], wq[d * D + t], a);
        qs[t] = a;
    } else if (t < 2 * D) {
        const int c = t - D;
        float a = bk[c];
        #pragma unroll
        for (int d = 0; d < D; ++d) a = fmaf(xs[d], wk[d * D + c], a);
        ks[c] = a;
    } else if (t < 3 * D) {
        const int c = t - 2 * D;
        float a = bv[c];
        #pragma unroll
        for (int d = 0; d < D; ++d) a = fmaf(xs[d], wv[d * D + c], a);
        g_v[row * D + c] = a;
    }
    __syncthreads();

    const int h = t;  // 0..127
    float qa = 0.f, qb = 0.f;
    float kb = nn_b1[h], ka = nn_b1[h];
    #pragma unroll
    for (int d = 0; d < D; ++d) {
        const float w1q = nn_w1[d * H + h];
        const float w1k = nn_w1[(d + D) * H + h];
        qa = fmaf(qs[d], w1q, qa);
        qb = fmaf(qs[d], w1k, qb);
        kb = fmaf(ks[d], w1k, kb);
        ka = fmaf(ks[d], w1q, ka);
    }
    g_qa [row * H + h] = qa;
    g_qb [row * H + h] = qb;
    g_kbp[row * H + h] = kb;
    g_kap[row * H + h] = ka;
}

// ---------------------------------------------------------------------------
// Kernel 2: fused logits -> softmax -> ctx -> wo -> LN1 -> FFN -> LN2
// grid = 128 blocks, 512 threads, ~213KB dyn smem, double-buffered kb/ka tiles
// ---------------------------------------------------------------------------
struct __align__(16) Smem {
    float kb[2][TJ * HPAD];    // double buffer
    float ka[2][TJ * HPAD];
    float qa[TI * HPAD];
    float qb[TI * HPAD];
    float logits[TI * L];
    float v[L * D];
    float w2[H];
    float wo[D * D];
    float f1[D * DFF];
    float f2[DFF * D];
    float hidden[TI * DFF];
    float ctxp[2][TI * D];
    float fp[2][TI * D];
    float xr[TI * D];
    float ctx[TI * D];
    float out1[TI * D];
    float f1b[DFF];
    float bo[D], f2b[D];
    float g1[D], be1[D], g2[D], be2[D];
};

__device__ __forceinline__ void prefetch_tile(Smem* s, int buf, int b, int t, int tid)
{
    const float4* gk = reinterpret_cast<const float4*>(g_kbp + (b * L + t * TJ) * H);
    const float4* ga = reinterpret_cast<const float4*>(g_kap + (b * L + t * TJ) * H);
    float4* skb = reinterpret_cast<float4*>(s->kb[buf]);
    float4* ska = reinterpret_cast<float4*>(s->ka[buf]);
    #pragma unroll
    for (int r = 0; r < 4; ++r) {
        const int idx = tid + 512 * r;                // < 2048
        const int dst = (idx >> 5) * 33 + (idx & 31); // padded f4 layout
        unsigned d1 = (unsigned)__cvta_generic_to_shared(skb + dst);
        unsigned d2 = (unsigned)__cvta_generic_to_shared(ska + dst);
        asm volatile("cp.async.cg.shared.global [%0], [%1], 16;" :: "r"(d1), "l"(gk + idx) : "memory");
        asm volatile("cp.async.cg.shared.global [%0], [%1], 16;" :: "r"(d2), "l"(ga + idx) : "memory");
    }
}

__global__ __launch_bounds__(512, 1) void k_main(
    const float* __restrict__ x,
    const float* __restrict__ mask,
    const float* __restrict__ wo_g, const float* __restrict__ bo_g,
    const float* __restrict__ w2_g, const float* __restrict__ b2_g,
    const float* __restrict__ f1_g, const float* __restrict__ f1b_g,
    const float* __restrict__ f2_g, const float* __restrict__ f2b_g,
    const float* __restrict__ g1_g, const float* __restrict__ be1_g,
    const float* __restrict__ g2_g, const float* __restrict__ be2_g,
    float* __restrict__ out)
{
    extern __shared__ char smem_raw[];
    Smem* s = reinterpret_cast<Smem*>(smem_raw);

    const int tid   = threadIdx.x;
    const int b     = blockIdx.x >> 4;
    const int iBase = (blockIdx.x & 15) << 4;

    // Prefetch first two kb/ka tiles immediately (overlaps with phase-0 fills)
    prefetch_tile(s, 0, b, 0, tid);
    asm volatile("cp.async.commit_group;" ::: "memory");
    prefetch_tile(s, 1, b, 1, tid);
    asm volatile("cp.async.commit_group;" ::: "memory");

    // ---------------- Phase 0: cooperative smem fills ----------------
    {
        const float4* gqa = reinterpret_cast<const float4*>(g_qa + (b * L + iBase) * H);
        const float4* gqb = reinterpret_cast<const float4*>(g_qb + (b * L + iBase) * H);
        float4* sqa = reinterpret_cast<float4*>(s->qa);
        float4* sqb = reinterpret_cast<float4*>(s->qb);
        {
            const int ir = tid >> 5, h4 = tid & 31;  // 512 == 16*32
            sqa[ir * 33 + h4] = gqa[tid];
            sqb[ir * 33 + h4] = gqb[tid];
        }
        const float4* gv = reinterpret_cast<const float4*>(g_v + b * L * D);
        float4* sv = reinterpret_cast<float4*>(s->v);
        sv[tid]       = gv[tid];
        sv[tid + 512] = gv[tid + 512];
        reinterpret_cast<float4*>(s->f1)[tid] = reinterpret_cast<const float4*>(f1_g)[tid];
        reinterpret_cast<float4*>(s->f2)[tid] = reinterpret_cast<const float4*>(f2_g)[tid];
        if (tid < H)   { s->w2[tid] = w2_g[tid]; s->f1b[tid] = f1b_g[tid]; }
        if (tid < 256) {
            s->wo[tid] = wo_g[tid];
            s->xr[tid] = x[(b * L + iBase) * D + tid];
        }
        if (tid < D) {
            s->bo[tid]  = bo_g[tid];  s->f2b[tid] = f2b_g[tid];
            s->g1[tid]  = g1_g[tid];  s->be1[tid] = be1_g[tid];
            s->g2[tid]  = g2_g[tid];  s->be2[tid] = be2_g[tid];
        }
    }

    // ---------------- Phase 1: pairwise-MLP logits ----------------
    const int j  = tid & 63;        // key column within tile
    const int ig = tid >> 6;        // 0..7 -> i pair (2 rows)
    const int i0 = ig * 2;

    const ulonglong2* qaA = reinterpret_cast<const ulonglong2*>(s->qa + (i0    ) * HPAD);
    const ulonglong2* qaB = reinterpret_cast<const ulonglong2*>(s->qa + (i0 + 1) * HPAD);
    const ulonglong2* qbA = reinterpret_cast<const ulonglong2*>(s->qb + (i0    ) * HPAD);
    const ulonglong2* qbB = reinterpret_cast<const ulonglong2*>(s->qb + (i0 + 1) * HPAD);
    const ulonglong2* w2p = reinterpret_cast<const ulonglong2*>(s->w2);

    for (int jt = 0; jt < 4; ++jt) {
        if (jt == 3) asm volatile("cp.async.wait_group 0;" ::: "memory");
        else         asm volatile("cp.async.wait_group 1;" ::: "memory");
        __syncthreads();   // tile jt visible to all; phase-0 fills done (jt=0)

        const ulonglong2* kbr = reinterpret_cast<const ulonglong2*>(s->kb[jt & 1]) + j * 33;
        const ulonglong2* kar = reinterpret_cast<const ulonglong2*>(s->ka[jt & 1]) + j * 33;

        u64 acc0 = 0ull, acc1 = 0ull;
        #pragma unroll 8
        for (int h4 = 0; h4 < 32; ++h4) {
            const ulonglong2 K = kbr[h4];
            const ulonglong2 A = kar[h4];
            const ulonglong2 W = w2p[h4];
            const ulonglong2 a0 = qaA[h4], a1 = qaB[h4];
            const ulonglong2 b0 = qbA[h4], b1 = qbB[h4];
            // half x (h, h+1)
            acc0 = fma2(add2(relu2(add2(a0.x, K.x)), relu2(add2(b0.x, A.x))), W.x, acc0);
            acc1 = fma2(add2(relu2(add2(a1.x, K.x)), relu2(add2(b1.x, A.x))), W.x, acc1);
            // half y (h+2, h+3)
            acc0 = fma2(add2(relu2(add2(a0.y, K.y)), relu2(add2(b0.y, A.y))), W.y, acc0);
            acc1 = fma2(add2(relu2(add2(a1.y, K.y)), relu2(add2(b1.y, A.y))), W.y, acc1);
        }
        const int jcol = jt * TJ + j;
        s->logits[(i0    ) * L + jcol] = redu2(acc0);
        s->logits[(i0 + 1) * L + jcol] = redu2(acc1);

        __syncthreads();   // everyone done reading buf[jt&1]
        if (jt < 2) prefetch_tile(s, jt & 1, b, jt + 2, tid);
        asm volatile("cp.async.commit_group;" ::: "memory");
    }
    __syncthreads();

    // ---------------- Phase 2: softmax (+mask, +2*b2), 16 warps x 16 rows ---
    {
        const int warp = tid >> 5, lane = tid & 31;
        const float b2x2 = 2.f * b2_g[0];
        const int r = warp;  // exactly 16 warps
        const float* mrow = mask + (size_t)(b * L + iBase + r) * L;
        float vals[8];
        float mx = -INFINITY;
        #pragma unroll
        for (int t = 0; t < 8; ++t) {
            const int jj = lane + 32 * t;
            const float lg = s->logits[r * L + jj] + b2x2 + mrow[jj] * (-1e9f);
            vals[t] = lg;
            mx = fmaxf(mx, lg);
        }
        #pragma unroll
        for (int m = 16; m > 0; m >>= 1)
            mx = fmaxf(mx, __shfl_xor_sync(0xffffffffu, mx, m));
        float sum = 0.f;
        #pragma unroll
        for (int t = 0; t < 8; ++t) { vals[t] = __expf(vals[t] - mx); sum += vals[t]; }
        #pragma unroll
        for (int m = 16; m > 0; m >>= 1)
            sum += __shfl_xor_sync(0xffffffffu, sum, m);
        const float inv = 1.f / sum;
        #pragma unroll
        for (int t = 0; t < 8; ++t)
            s->logits[r * L + lane + 32 * t] = vals[t] * inv;
    }
    __syncthreads();

    // ---------------- Phase 3: ctx = attn @ v (split over 2 j-halves) ------
    {
        const int p  = tid & 255;
        const int hf = tid >> 8;
        const int il = p >> 4, dl = p & 15;
        float c = 0.f;
        const float* arow = s->logits + il * L + hf * 128;
        const float* vv   = s->v + hf * 128 * D + dl;
        #pragma unroll 8
        for (int jj = 0; jj < 128; ++jj)
            c = fmaf(arow[jj], vv[jj * D], c);
        s->ctxp[hf][p] = c;
    }
    __syncthreads();

    // attn_out + residual + LN1 (first 256 threads)
    if (tid < 256) {
        const int il = tid >> 4, dl = tid & 15;
        s->ctx[tid] = s->ctxp[0][tid] + s->ctxp[1][tid];
        __syncwarp();
        float ao = s->bo[dl];
        #pragma unroll
        for (int e = 0; e < D; ++e)
            ao = fmaf(s->ctxp[0][il * D + e] + s->ctxp[1][il * D + e], s->wo[e * D + dl], ao);
        const float hval = s->xr[tid] + ao;   // RES=1
        float m = hval, sq = hval * hval;
        #pragma unroll
        for (int msk = 8; msk > 0; msk >>= 1) {
            m  += __shfl_xor_sync(0xffffffffu, m,  msk);
            sq += __shfl_xor_sync(0xffffffffu, sq, msk);
        }
        m *= (1.f / 16.f);
        const float var = sq * (1.f / 16.f) - m * m;
        s->out1[tid] = (hval - m) * rsqrtf(var + EPSV) * s->g1[dl] + s->be1[dl];
    }
    __syncthreads();

    // ---------------- Phase 4: FFN hidden (512 threads, 4 i's each) --------
    {
        const int h   = tid & 127;
        const int ig4 = tid >> 7;     // 0..3
        #pragma unroll
        for (int c = 0; c < 4; ++c) {
            const int il = ig4 * 4 + c;
            float acc = s->f1b[h];
            #pragma unroll
            for (int d = 0; d < D; ++d)
                acc = fmaf(s->out1[il * D + d], s->f1[d * DFF + h], acc);
            s->hidden[il * DFF + h] = fmaxf(acc, 0.f);
        }
    }
    __syncthreads();

    // f2 contraction split over 2 h-halves
    {
        const int p  = tid & 255;
        const int hf = tid >> 8;
        const int il = p >> 4, dl = p & 15;
        float f = 0.f;
        const float* hrow = s->hidden + il * DFF + hf * 64;
        const float* ff   = s->f2 + hf * 64 * D + dl;
        #pragma unroll 8
        for (int hh = 0; hh < 64; ++hh)
            f = fmaf(hrow[hh], ff[hh * D], f);
        s->fp[hf][p] = f;
    }
    __syncthreads();

    if (tid < 256) {
        const int il = tid >> 4, dl = tid & 15;
        const float f = s->f2b[dl] + s->fp[0][tid] + s->fp[1][tid];
        const float hval = s->out1[tid] + f;   // RES=1
        float m = hval, sq = hval * hval;
        #pragma unroll
        for (int msk = 8; msk > 0; msk >>= 1) {
            m  += __shfl_xor_sync(0xffffffffu, m,  msk);
            sq += __shfl_xor_sync(0xffffffffu, sq, msk);
        }
        m *= (1.f / 16.f);
        const float var = sq * (1.f / 16.f) - m * m;
        const float o = (hval - m) * rsqrtf(var + EPSV) * s->g2[dl] + s->be2[dl];
        out[(size_t)(b * L + iBase + il) * D + dl] = o;
    }
}

// ---------------------------------------------------------------------------
extern "C" void kernel_launch(void* const* d_in, const int* in_sizes, int n_in,
                              void* d_out, int out_size)
{
    const float* x     = (const float*)d_in[0];
    const float* mask  = (const float*)d_in[1];
    const float* wq    = (const float*)d_in[2];
    const float* bq    = (const float*)d_in[3];
    const float* wk    = (const float*)d_in[4];
    const float* bk    = (const float*)d_in[5];
    const float* wv    = (const float*)d_in[6];
    const float* bv    = (const float*)d_in[7];
    const float* wo    = (const float*)d_in[8];
    const float* bo    = (const float*)d_in[9];
    const float* nn_w1 = (const float*)d_in[10];
    const float* nn_b1 = (const float*)d_in[11];
    const float* nn_w2 = (const float*)d_in[12];
    const float* nn_b2 = (const float*)d_in[13];
    const float* f1    = (const float*)d_in[14];
    const float* f1b   = (const float*)d_in[15];
    const float* f2    = (const float*)d_in[16];
    const float* f2b   = (const float*)d_in[17];
    const float* g1    = (const float*)d_in[18];
    const float* be1   = (const float*)d_in[19];
    const float* g2    = (const float*)d_in[20];
    const float* be2   = (const float*)d_in[21];
    float* out = (float*)d_out;

    cudaFuncSetAttribute(k_main, cudaFuncAttributeMaxDynamicSharedMemorySize,
                         (int)sizeof(Smem));

    k_precompute<<<B * L, 128>>>(x, wq, bq, wk, bk, wv, bv, nn_w1, nn_b1);
    k_main<<<B * (L / TI), 512, sizeof(Smem)>>>(
        x, mask, wo, bo, nn_w2, nn_b2, f1, f1b, f2, f2b, g1, be1, g2, be2, out);
}

// round 3
// speedup vs baseline: 1.3231x; 1.1959x over previous
#include <cuda_runtime.h>
#include <math.h>

// Problem constants
#define B 8
#define L 256
#define D 16
#define H 128      // H_NN
#define DFF 128
#define EPSV 1e-6f

#define TI 16       // query rows per block
#define RI 8        // i-rows per thread
#define CH 32       // h per chunk
#define NCH 4       // chunks (NCH*CH = H)
#define CHF4 8      // f4 per row per chunk
#define CHPAD9 9    // padded f4 row stride in chunk buffer (36 floats)

typedef unsigned long long u64;

// Scratch (device globals, allocation-free)
__device__ float g_v  [B * L * D];
__device__ float g_qa [B * L * H];
__device__ float g_qb [B * L * H];
__device__ float g_kbp[B * L * H];   // k@w1k + b1
__device__ float g_kap[B * L * H];   // k@w1q + b1

// ---------------- packed f32x2 helpers ----------------
__device__ __forceinline__ u64 add2(u64 a, u64 b) {
    u64 d; asm("add.rn.f32x2 %0,%1,%2;" : "=l"(d) : "l"(a), "l"(b)); return d;
}
__device__ __forceinline__ u64 fma2(u64 a, u64 b, u64 c) {
    u64 d; asm("fma.rn.f32x2 %0,%1,%2,%3;" : "=l"(d) : "l"(a), "l"(b), "l"(c)); return d;
}
__device__ __forceinline__ u64 relu2(u64 v) {
    float lo, hi;
    asm("mov.b64 {%0,%1}, %2;" : "=f"(lo), "=f"(hi) : "l"(v));
    lo = fmaxf(lo, 0.f); hi = fmaxf(hi, 0.f);
    u64 d; asm("mov.b64 %0,{%1,%2};" : "=l"(d) : "f"(lo), "f"(hi)); return d;
}
__device__ __forceinline__ float redu2(u64 v) {
    float lo, hi;
    asm("mov.b64 {%0,%1}, %2;" : "=f"(lo), "=f"(hi) : "l"(v));
    return lo + hi;
}

// ---------------------------------------------------------------------------
// Kernel 1: per-token projections + MLP pre-activations
// ---------------------------------------------------------------------------
__global__ __launch_bounds__(128) void k_precompute(
    const float* __restrict__ x,
    const float* __restrict__ wq, const float* __restrict__ bq,
    const float* __restrict__ wk, const float* __restrict__ bk,
    const float* __restrict__ wv, const float* __restrict__ bv,
    const float* __restrict__ nn_w1, const float* __restrict__ nn_b1)
{
    __shared__ float xs[D], qs[D], ks[D];
    const int row = blockIdx.x;          // b*256 + l
    const int t = threadIdx.x;

    if (t < D) xs[t] = x[row * D + t];
    __syncthreads();

    if (t < D) {
        float a = bq[t];
        #pragma unroll
        for (int d = 0; d < D; ++d) a = fmaf(xs[d], wq[d * D + t], a);
        qs[t] = a;
    } else if (t < 2 * D) {
        const int c = t - D;
        float a = bk[c];
        #pragma unroll
        for (int d = 0; d < D; ++d) a = fmaf(xs[d], wk[d * D + c], a);
        ks[c] = a;
    } else if (t < 3 * D) {
        const int c = t - 2 * D;
        float a = bv[c];
        #pragma unroll
        for (int d = 0; d < D; ++d) a = fmaf(xs[d], wv[d * D + c], a);
        g_v[row * D + c] = a;
    }
    __syncthreads();

    const int h = t;  // 0..127
    float qa = 0.f, qb = 0.f;
    float kb = nn_b1[h], ka = nn_b1[h];
    #pragma unroll
    for (int d = 0; d < D; ++d) {
        const float w1q = nn_w1[d * H + h];
        const float w1k = nn_w1[(d + D) * H + h];
        qa = fmaf(qs[d], w1q, qa);
        qb = fmaf(qs[d], w1k, qb);
        kb = fmaf(ks[d], w1k, kb);
        ka = fmaf(ks[d], w1q, ka);
    }
    g_qa [row * H + h] = qa;
    g_qb [row * H + h] = qb;
    g_kbp[row * H + h] = kb;
    g_kap[row * H + h] = ka;
}

// ---------------------------------------------------------------------------
// Kernel 2: fused logits -> softmax -> ctx -> wo -> LN1 -> FFN -> LN2
// 128 blocks x 512 threads. Each thread: RI=8 i-rows, fixed j, h streamed
// in 4 chunks of 32 through double-buffered cp.async chunk buffers.
// ---------------------------------------------------------------------------
struct __align__(16) Smem {
    float kb[2][L * CHPAD9 * 4];   // 2 buffers, 256 rows x 36 floats
    float ka[2][L * CHPAD9 * 4];
    float qa[TI * 132];
    float qb[TI * 132];
    float logits[TI * L];
    float vT[D * 260];             // transposed v, padded
    float w2[H];
    float wo[D * D];
    float f1[D * DFF];
    float f2T[D * 132];            // transposed f2, padded
    float xr[TI * D];
    float out1[TI * D];
    float f1b[DFF];
    float bo[D], f2b[D];
    float g1[D], be1[D], g2[D], be2[D];
    // aliased (phase-disjoint) regions:
    //   hidden -> kb[0][0..2047]
    //   ctxp0/1, fp0/1 -> ka[0][0..1023]
};

__device__ __forceinline__ void prefetch_chunk(Smem* s, int buf, int b, int c, int tid)
{
    const float4* gk = reinterpret_cast<const float4*>(g_kbp + b * L * H);
    const float4* ga = reinterpret_cast<const float4*>(g_kap + b * L * H);
    float4* skb = reinterpret_cast<float4*>(s->kb[buf]);
    float4* ska = reinterpret_cast<float4*>(s->ka[buf]);
    #pragma unroll
    for (int r = 0; r < 4; ++r) {
        const int idx = tid + 512 * r;                 // < 2048
        const int row = idx >> 3, h8 = idx & 7;
        const int dst = row * CHPAD9 + h8;             // f4 units
        const int src = row * 32 + c * CHF4 + h8;      // f4 units
        unsigned d1 = (unsigned)__cvta_generic_to_shared(skb + dst);
        unsigned d2 = (unsigned)__cvta_generic_to_shared(ska + dst);
        asm volatile("cp.async.cg.shared.global [%0], [%1], 16;" :: "r"(d1), "l"(gk + src) : "memory");
        asm volatile("cp.async.cg.shared.global [%0], [%1], 16;" :: "r"(d2), "l"(ga + src) : "memory");
    }
}

__global__ __launch_bounds__(512, 1) void k_main(
    const float* __restrict__ x,
    const float* __restrict__ mask,
    const float* __restrict__ wo_g, const float* __restrict__ bo_g,
    const float* __restrict__ w2_g, const float* __restrict__ b2_g,
    const float* __restrict__ f1_g, const float* __restrict__ f1b_g,
    const float* __restrict__ f2_g, const float* __restrict__ f2b_g,
    const float* __restrict__ g1_g, const float* __restrict__ be1_g,
    const float* __restrict__ g2_g, const float* __restrict__ be2_g,
    float* __restrict__ out)
{
    extern __shared__ char smem_raw[];
    Smem* s = reinterpret_cast<Smem*>(smem_raw);

    const int tid   = threadIdx.x;
    const int b     = blockIdx.x >> 4;
    const int iBase = (blockIdx.x & 15) << 4;

    // Prefetch first two h-chunks of kb/ka
    prefetch_chunk(s, 0, b, 0, tid);
    asm volatile("cp.async.commit_group;" ::: "memory");
    prefetch_chunk(s, 1, b, 1, tid);
    asm volatile("cp.async.commit_group;" ::: "memory");

    // ---------------- Phase 0: cooperative smem fills ----------------
    {
        // qa/qb: 16 rows x 32 f4, padded stride 33 f4
        const float4* gqa = reinterpret_cast<const float4*>(g_qa + (b * L + iBase) * H);
        const float4* gqb = reinterpret_cast<const float4*>(g_qb + (b * L + iBase) * H);
        float4* sqa = reinterpret_cast<float4*>(s->qa);
        float4* sqb = reinterpret_cast<float4*>(s->qb);
        {
            const int ir = tid >> 5, h4 = tid & 31;    // 512 = 16*32
            sqa[ir * 33 + h4] = gqa[tid];
            sqb[ir * 33 + h4] = gqb[tid];
        }
        // vT: transpose v[j][d] -> vT[d][260]
        const float4* gv = reinterpret_cast<const float4*>(g_v + b * L * D);
        #pragma unroll
        for (int r = 0; r < 2; ++r) {
            const int e = tid + 512 * r;               // < 1024
            const float4 val = gv[e];
            const int j = e >> 2, dq = e & 3;
            s->vT[(dq * 4 + 0) * 260 + j] = val.x;
            s->vT[(dq * 4 + 1) * 260 + j] = val.y;
            s->vT[(dq * 4 + 2) * 260 + j] = val.z;
            s->vT[(dq * 4 + 3) * 260 + j] = val.w;
        }
        // f2T: transpose f2[h][d] -> f2T[d][132]
        #pragma unroll
        for (int r = 0; r < 4; ++r) {
            const int e = tid + 512 * r;               // < 2048
            const int h = e >> 4, d = e & 15;
            s->f2T[d * 132 + h] = f2_g[e];
        }
        reinterpret_cast<float4*>(s->f1)[tid] = reinterpret_cast<const float4*>(f1_g)[tid];
        if (tid < H)   { s->w2[tid] = w2_g[tid]; s->f1b[tid] = f1b_g[tid]; }
        if (tid < 256) {
            s->wo[tid] = wo_g[tid];
            s->xr[tid] = x[(b * L + iBase) * D + tid];
        }
        if (tid < D) {
            s->bo[tid]  = bo_g[tid];  s->f2b[tid] = f2b_g[tid];
            s->g1[tid]  = g1_g[tid];  s->be1[tid] = be1_g[tid];
            s->g2[tid]  = g2_g[tid];  s->be2[tid] = be2_g[tid];
        }
    }

    // ---------------- Phase 1: pairwise-MLP logits ----------------
    const int j = tid & 255;       // fixed key column
    const int g = tid >> 8;        // 0/1 -> i-rows 0-7 / 8-15

    const ulonglong2* qaR[RI];
    const ulonglong2* qbR[RI];
    #pragma unroll
    for (int r = 0; r < RI; ++r) {
        qaR[r] = reinterpret_cast<const ulonglong2*>(s->qa + (g * RI + r) * 132);
        qbR[r] = reinterpret_cast<const ulonglong2*>(s->qb + (g * RI + r) * 132);
    }
    const ulonglong2* w2p = reinterpret_cast<const ulonglong2*>(s->w2);

    u64 acc[RI];
    #pragma unroll
    for (int r = 0; r < RI; ++r) acc[r] = 0ull;

    for (int c = 0; c < NCH; ++c) {
        if (c < NCH - 1) asm volatile("cp.async.wait_group 1;" ::: "memory");
        else             asm volatile("cp.async.wait_group 0;" ::: "memory");
        __syncthreads();   // chunk c visible; (c=0) phase-0 fills done

        const ulonglong2* kbr = reinterpret_cast<const ulonglong2*>(s->kb[c & 1]) + j * CHPAD9;
        const ulonglong2* kar = reinterpret_cast<const ulonglong2*>(s->ka[c & 1]) + j * CHPAD9;
        const int cbase = c * CHF4;

        #pragma unroll
        for (int h8 = 0; h8 < CHF4; ++h8) {
            const ulonglong2 K = kbr[h8];
            const ulonglong2 A = kar[h8];
            const ulonglong2 W = w2p[cbase + h8];
            #pragma unroll
            for (int r = 0; r < RI; ++r) {
                const ulonglong2 a = qaR[r][cbase + h8];
                const ulonglong2 bb = qbR[r][cbase + h8];
                acc[r] = fma2(add2(relu2(add2(a.x, K.x)), relu2(add2(bb.x, A.x))), W.x, acc[r]);
                acc[r] = fma2(add2(relu2(add2(a.y, K.y)), relu2(add2(bb.y, A.y))), W.y, acc[r]);
            }
        }

        __syncthreads();   // everyone done reading buf[c&1]
        if (c + 2 < NCH + 0 || c + 2 == NCH - 0) {}  // no-op
        if (c + 2 <= NCH - 1) {
            prefetch_chunk(s, c & 1, b, c + 2, tid);
        }
        asm volatile("cp.async.commit_group;" ::: "memory");
    }

    #pragma unroll
    for (int r = 0; r < RI; ++r)
        s->logits[(g * RI + r) * L + j] = redu2(acc[r]);
    __syncthreads();

    // ---------------- Phase 2: softmax (+mask, +2*b2), 16 warps x 16 rows ---
    {
        const int warp = tid >> 5, lane = tid & 31;
        const float b2x2 = 2.f * b2_g[0];
        const int r = warp;
        const float* mrow = mask + (size_t)(b * L + iBase + r) * L;
        float vals[8];
        float mx = -INFINITY;
        #pragma unroll
        for (int t = 0; t < 8; ++t) {
            const int jj = lane + 32 * t;
            const float lg = s->logits[r * L + jj] + b2x2 + mrow[jj] * (-1e9f);
            vals[t] = lg;
            mx = fmaxf(mx, lg);
        }
        #pragma unroll
        for (int m = 16; m > 0; m >>= 1)
            mx = fmaxf(mx, __shfl_xor_sync(0xffffffffu, mx, m));
        float sum = 0.f;
        #pragma unroll
        for (int t = 0; t < 8; ++t) { vals[t] = __expf(vals[t] - mx); sum += vals[t]; }
        #pragma unroll
        for (int m = 16; m > 0; m >>= 1)
            sum += __shfl_xor_sync(0xffffffffu, sum, m);
        const float inv = 1.f / sum;
        #pragma unroll
        for (int t = 0; t < 8; ++t)
            s->logits[r * L + lane + 32 * t] = vals[t] * inv;
    }
    __syncthreads();

    // Aliased scratch (phase-disjoint with kb/ka chunk buffers)
    float* hidden = s->kb[0];          // TI*DFF = 2048 floats
    float* ctxp0  = s->ka[0];          // 256 floats
    float* ctxp1  = s->ka[0] + 256;
    float* fp0    = s->ka[0] + 512;
    float* fp1    = s->ka[0] + 768;

    // ---------------- Phase 3: ctx = attn @ v (vT, float4) ----------------
    {
        const int p  = tid & 255;
        const int hf = tid >> 8;
        const int il = p >> 4, dl = p & 15;
        const float4* arow = reinterpret_cast<const float4*>(s->logits + il * L + hf * 128);
        const float4* vrow = reinterpret_cast<const float4*>(s->vT + dl * 260 + hf * 128);
        float c = 0.f;
        #pragma unroll 8
        for (int q = 0; q < 32; ++q) {
            const float4 a4 = arow[q];
            const float4 v4 = vrow[q];
            c = fmaf(a4.x, v4.x, c);
            c = fmaf(a4.y, v4.y, c);
            c = fmaf(a4.z, v4.z, c);
            c = fmaf(a4.w, v4.w, c);
        }
        (hf ? ctxp1 : ctxp0)[p] = c;
    }
    __syncthreads();

    // attn_out + residual + LN1 (first 256 threads)
    if (tid < 256) {
        const int il = tid >> 4, dl = tid & 15;
        float ao = s->bo[dl];
        #pragma unroll
        for (int e = 0; e < D; ++e)
            ao = fmaf(ctxp0[il * D + e] + ctxp1[il * D + e], s->wo[e * D + dl], ao);
        const float hval = s->xr[tid] + ao;   // RES=1
        float m = hval, sq = hval * hval;
        #pragma unroll
        for (int msk = 8; msk > 0; msk >>= 1) {
            m  += __shfl_xor_sync(0xffffffffu, m,  msk);
            sq += __shfl_xor_sync(0xffffffffu, sq, msk);
        }
        m *= (1.f / 16.f);
        const float var = sq * (1.f / 16.f) - m * m;
        s->out1[tid] = (hval - m) * rsqrtf(var + EPSV) * s->g1[dl] + s->be1[dl];
    }
    __syncthreads();

    // ---------------- Phase 4: FFN hidden (512 threads, 4 i's each) --------
    {
        const int h   = tid & 127;
        const int ig4 = tid >> 7;     // 0..3
        #pragma unroll
        for (int c = 0; c < 4; ++c) {
            const int il = ig4 * 4 + c;
            float acc2 = s->f1b[h];
            #pragma unroll
            for (int d = 0; d < D; ++d)
                acc2 = fmaf(s->out1[il * D + d], s->f1[d * DFF + h], acc2);
            hidden[il * DFF + h] = fmaxf(acc2, 0.f);
        }
    }
    __syncthreads();

    // f2 contraction (f2T, float4), split over 2 h-halves
    {
        const int p  = tid & 255;
        const int hf = tid >> 8;
        const int il = p >> 4, dl = p & 15;
        const float4* hrow = reinterpret_cast<const float4*>(hidden + il * DFF + hf * 64);
        const float4* frow = reinterpret_cast<const float4*>(s->f2T + dl * 132 + hf * 64);
        float f = 0.f;
        #pragma unroll 8
        for (int q = 0; q < 16; ++q) {
            const float4 h4 = hrow[q];
            const float4 f4 = frow[q];
            f = fmaf(h4.x, f4.x, f);
            f = fmaf(h4.y, f4.y, f);
            f = fmaf(h4.z, f4.z, f);
            f = fmaf(h4.w, f4.w, f);
        }
        (hf ? fp1 : fp0)[p] = f;
    }
    __syncthreads();

    if (tid < 256) {
        const int il = tid >> 4, dl = tid & 15;
        const float f = s->f2b[dl] + fp0[tid] + fp1[tid];
        const float hval = s->out1[tid] + f;   // RES=1
        float m = hval, sq = hval * hval;
        #pragma unroll
        for (int msk = 8; msk > 0; msk >>= 1) {
            m  += __shfl_xor_sync(0xffffffffu, m,  msk);
            sq += __shfl_xor_sync(0xffffffffu, sq, msk);
        }
        m *= (1.f / 16.f);
        const float var = sq * (1.f / 16.f) - m * m;
        const float o = (hval - m) * rsqrtf(var + EPSV) * s->g2[dl] + s->be2[dl];
        out[(size_t)(b * L + iBase + il) * D + dl] = o;
    }
}

// ---------------------------------------------------------------------------
extern "C" void kernel_launch(void* const* d_in, const int* in_sizes, int n_in,
                              void* d_out, int out_size)
{
    const float* x     = (const float*)d_in[0];
    const float* mask  = (const float*)d_in[1];
    const float* wq    = (const float*)d_in[2];
    const float* bq    = (const float*)d_in[3];
    const float* wk    = (const float*)d_in[4];
    const float* bk    = (const float*)d_in[5];
    const float* wv    = (const float*)d_in[6];
    const float* bv    = (const float*)d_in[7];
    const float* wo    = (const float*)d_in[8];
    const float* bo    = (const float*)d_in[9];
    const float* nn_w1 = (const float*)d_in[10];
    const float* nn_b1 = (const float*)d_in[11];
    const float* nn_w2 = (const float*)d_in[12];
    const float* nn_b2 = (const float*)d_in[13];
    const float* f1    = (const float*)d_in[14];
    const float* f1b   = (const float*)d_in[15];
    const float* f2    = (const float*)d_in[16];
    const float* f2b   = (const float*)d_in[17];
    const float* g1    = (const float*)d_in[18];
    const float* be1   = (const float*)d_in[19];
    const float* g2    = (const float*)d_in[20];
    const float* be2   = (const float*)d_in[21];
    float* out = (float*)d_out;

    cudaFuncSetAttribute(k_main, cudaFuncAttributeMaxDynamicSharedMemorySize,
                         (int)sizeof(Smem));

    k_precompute<<<B * L, 128>>>(x, wq, bq, wk, bk, wv, bv, nn_w1, nn_b1);
    k_main<<<B * (L / TI), 512, sizeof(Smem)>>>(
        x, mask, wo, bo, nn_w2, nn_b2, f1, f1b, f2, f2b, g1, be1, g2, be2, out);
}